// round 3
// baseline (speedup 1.0000x reference)
#include <cuda_runtime.h>
#include <math.h>

// ---------------- problem constants ----------------
#define Bg   32
#define NPG  2048
#define Nn   (Bg*NPG)        // 65536
#define Ee   (Nn*8)          // 524288
#define IND  64
#define H1   128
#define H2   256
#define K1   1024
#define K2   512
#define N1   (Bg*K1)         // 32768
#define N2   (Bg*K2)         // 16384

// ---------------- scratch (device globals; no allocs) ----------------
// stage-1 zero region: [agg1 | cnt1 | sseg1 | bnacc1]
#define Z1_FLOATS (Nn*IND + Nn + Nn + 2*H1)
__device__ float g_z1[Z1_FLOATS];
// stage-2 zero region: [agg2 | cnt2 | sseg2 | bnacc2]
#define Z2_FLOATS (N1*H1 + N1 + N1 + 2*H2)
__device__ float g_z2[Z2_FLOATS];

__device__ float g_rrel1[Nn];
__device__ float g_rroot1[Nn];
__device__ float g_pre1 [Nn*H1];
__device__ int   g_map1 [Nn];
__device__ int   g_perm1[N1];
__device__ float g_tanh1[N1];
__device__ int   g_src2 [Ee];
__device__ int   g_tgt2 [Ee];
__device__ float g_h1new[N1*H1];
__device__ float g_rrel2[N1];
__device__ float g_rroot2[N1];
__device__ float g_pre2 [N1*H2];
__device__ int   g_perm2[N2];
__device__ float g_tanh2[N2];
__device__ float g_scale[H2];
__device__ float g_shift[H2];
__device__ int   g_ctr1 = 0;
__device__ int   g_ctr2 = 0;

// ---------------- f32x2 helpers ----------------
__device__ __forceinline__ unsigned long long pk2(float lo, float hi) {
    unsigned long long r;
    asm("mov.b64 %0, {%1,%2};" : "=l"(r) : "f"(lo), "f"(hi));
    return r;
}
__device__ __forceinline__ void upk2(unsigned long long v, float& lo, float& hi) {
    asm("mov.b64 {%0,%1}, %2;" : "=f"(lo), "=f"(hi) : "l"(v));
}
__device__ __forceinline__ void ffma2(unsigned long long& d, unsigned long long a, unsigned long long b) {
    asm("fma.rn.f32x2 %0, %1, %2, %0;" : "+l"(d) : "l"(a), "l"(b));
}

// ---------------- kernels ----------------

// vectorized mean aggregation over edges: one thread per (edge, float4)
template<int D>
__global__ void agg_kernel(const int* __restrict__ src, const int* __restrict__ tgt,
                           const float* __restrict__ xin, float* __restrict__ aggo,
                           float* __restrict__ cnt, int nedges)
{
    const int V = D / 4;
    int i = blockIdx.x * blockDim.x + threadIdx.x;
    if (i >= nedges * V) return;
    int e  = i / V;
    int f4 = i - e * V;
    int s = src[e];
    if (s < 0) return;
    int t = tgt[e];
    float4 v = reinterpret_cast<const float4*>(xin)[(size_t)s * V + f4];
    asm volatile("red.global.add.v4.f32 [%0], {%1,%2,%3,%4};"
                 :: "l"(&aggo[(size_t)t * D + f4 * 4]),
                    "f"(v.x), "f"(v.y), "f"(v.z), "f"(v.w) : "memory");
    if (f4 == 0) atomicAdd(&cnt[t], 1.0f);
}

// pre[n,OD] = (agg[n]/max(cnt,1)) @ Wl + xin @ Wr + bias   (K concat, FFMA2)
// 256 threads; CG column-groups of TN=8 cols; 16 rows per thread (8 row-pairs).
// Fused: per-column sum/sumsq -> bnacc; last block computes BN scale/shift.
template<int KD, int OD, int CG>
__global__ void __launch_bounds__(256)
gemm_dual3(const float* __restrict__ agg, const float* __restrict__ cnt,
           const float* __restrict__ xin,
           const float* __restrict__ Wl, const float* __restrict__ Wr,
           const float* __restrict__ bias, float* __restrict__ outp,
           float* __restrict__ bnacc, int* __restrict__ ctr,
           const float* __restrict__ bng, const float* __restrict__ bnb,
           float* __restrict__ scale, float* __restrict__ shift,
           float invn)
{
    const int TN = 8, BK = 32;
    const int NTY = 256 / CG;            // row groups
    const int BM  = NTY * 16;            // rows per block
    const int ASTR = BM + 4;
    extern __shared__ float sh[];
    float* sW = sh;                      // BK*OD
    float* sA = sh + BK * OD;            // BK*ASTR

    int tid = threadIdx.x;
    int tx  = tid % CG;
    int ty  = tid / CG;
    int row0 = blockIdx.x * BM;

    unsigned long long acc[8][TN];
#pragma unroll
    for (int r = 0; r < 8; r++)
#pragma unroll
        for (int j = 0; j < TN; j++) acc[r][j] = 0ull;

    for (int kt = 0; kt < 2 * KD; kt += BK) {
        for (int i = tid; i < BK * OD; i += 256) {
            int k = i / OD, c = i - k * OD;
            int kg = kt + k;
            sW[i] = (kg < KD) ? Wl[(size_t)kg * OD + c] : Wr[(size_t)(kg - KD) * OD + c];
        }
        for (int i = tid; i < BM * BK; i += 256) {
            int m = i >> 5, k = i & 31;
            int kg = kt + k;
            int row = row0 + m;
            float v;
            if (kg < KD) v = agg[(size_t)row * KD + kg] * (1.f / fmaxf(cnt[row], 1.f));
            else         v = xin[(size_t)row * KD + (kg - KD)];
            sA[k * ASTR + m] = v;
        }
        __syncthreads();
#pragma unroll 4
        for (int k = 0; k < BK; k++) {
            const ulonglong2* apv = reinterpret_cast<const ulonglong2*>(&sA[k * ASTR + ty * 16]);
            ulonglong2 p0 = apv[0], p1 = apv[1], p2 = apv[2], p3 = apv[3];
            unsigned long long ap[8] = { p0.x, p0.y, p1.x, p1.y, p2.x, p2.y, p3.x, p3.y };
#pragma unroll
            for (int jj = 0; jj < TN / 4; jj++) {
                float4 w4 = *reinterpret_cast<const float4*>(&sW[k * OD + tx * TN + jj * 4]);
                unsigned long long w0 = pk2(w4.x, w4.x), w1 = pk2(w4.y, w4.y);
                unsigned long long w2 = pk2(w4.z, w4.z), w3 = pk2(w4.w, w4.w);
#pragma unroll
                for (int r = 0; r < 8; r++) {
                    ffma2(acc[r][jj*4+0], ap[r], w0);
                    ffma2(acc[r][jj*4+1], ap[r], w1);
                    ffma2(acc[r][jj*4+2], ap[r], w2);
                    ffma2(acc[r][jj*4+3], ap[r], w3);
                }
            }
        }
        __syncthreads();
    }

    // epilogue: unpack, add bias, store; accumulate col stats in regs
    float cs[TN], cs2[TN];
#pragma unroll
    for (int j = 0; j < TN; j++) { cs[j] = 0.f; cs2[j] = 0.f; }
    float bb[TN];
#pragma unroll
    for (int jj = 0; jj < TN / 4; jj++) {
        float4 b4 = *reinterpret_cast<const float4*>(&bias[tx * TN + jj * 4]);
        bb[jj*4+0]=b4.x; bb[jj*4+1]=b4.y; bb[jj*4+2]=b4.z; bb[jj*4+3]=b4.w;
    }
#pragma unroll
    for (int r = 0; r < 8; r++) {
        float lo[TN], hi[TN];
#pragma unroll
        for (int j = 0; j < TN; j++) {
            upk2(acc[r][j], lo[j], hi[j]);
            lo[j] += bb[j]; hi[j] += bb[j];
            cs[j]  += lo[j] + hi[j];
            cs2[j] += lo[j]*lo[j] + hi[j]*hi[j];
        }
        int row_lo = row0 + ty * 16 + 2 * r;
#pragma unroll
        for (int jj = 0; jj < TN / 4; jj++) {
            int c = tx * TN + jj * 4;
            *reinterpret_cast<float4*>(&outp[(size_t)row_lo * OD + c]) =
                make_float4(lo[jj*4], lo[jj*4+1], lo[jj*4+2], lo[jj*4+3]);
            *reinterpret_cast<float4*>(&outp[(size_t)(row_lo+1) * OD + c]) =
                make_float4(hi[jj*4], hi[jj*4+1], hi[jj*4+2], hi[jj*4+3]);
        }
    }

    // block-level stats reduction (reuse smem), then atomics
    float* sRed = sh;   // NTY*OD floats
#pragma unroll
    for (int j = 0; j < TN; j++) sRed[ty * OD + tx * TN + j] = cs[j];
    __syncthreads();
    for (int c = tid; c < OD; c += 256) {
        float t = 0.f;
#pragma unroll
        for (int i = 0; i < NTY; i++) t += sRed[i * OD + c];
        atomicAdd(&bnacc[c], t);
    }
    __syncthreads();
#pragma unroll
    for (int j = 0; j < TN; j++) sRed[ty * OD + tx * TN + j] = cs2[j];
    __syncthreads();
    for (int c = tid; c < OD; c += 256) {
        float t = 0.f;
#pragma unroll
        for (int i = 0; i < NTY; i++) t += sRed[i * OD + c];
        atomicAdd(&bnacc[OD + c], t);
    }

    // last block computes BN scale/shift
    __shared__ int sDone;
    __threadfence();
    if (tid == 0) {
        int old = atomicAdd(ctr, 1);
        sDone = (old == (int)gridDim.x - 1);
    }
    __syncthreads();
    if (sDone) {
        if (tid < OD) {
            float s  = __ldcg(&bnacc[tid]);
            float s2 = __ldcg(&bnacc[OD + tid]);
            float m   = s * invn;
            float var = s2 * invn - m * m;
            float sc  = rsqrtf(var + 1e-5f) * bng[tid];
            scale[tid] = sc;
            shift[tid] = bnb[tid] - m * sc;
        }
        if (tid == 0) *ctr = 0;
    }
}

// fused: BN apply (registers only) + ReLU + two score dot products. One warp per row.
template<int D>
__global__ void bnad_kernel(const float* __restrict__ pre, const float* __restrict__ scale,
                            const float* __restrict__ shift,
                            const float* __restrict__ wrel, const float* __restrict__ wroot,
                            float* __restrict__ rrel, float* __restrict__ rroot, int nrows)
{
    int w = (blockIdx.x * blockDim.x + threadIdx.x) >> 5;
    int lane = threadIdx.x & 31;
    if (w >= nrows) return;
    const int V = D / 128;
    float s1 = 0.f, s2 = 0.f;
    const float4* rowp = reinterpret_cast<const float4*>(pre + (size_t)w * D);
#pragma unroll
    for (int q = 0; q < V; q++) {
        int c4 = lane + q * 32;
        float4 v  = rowp[c4];
        float4 sc = reinterpret_cast<const float4*>(scale)[c4];
        float4 sh = reinterpret_cast<const float4*>(shift)[c4];
        v.x = fmaxf(fmaf(v.x, sc.x, sh.x), 0.f);
        v.y = fmaxf(fmaf(v.y, sc.y, sh.y), 0.f);
        v.z = fmaxf(fmaf(v.z, sc.z, sh.z), 0.f);
        v.w = fmaxf(fmaf(v.w, sc.w, sh.w), 0.f);
        float4 wr = reinterpret_cast<const float4*>(wrel)[c4];
        float4 wo = reinterpret_cast<const float4*>(wroot)[c4];
        s1 += v.x*wr.x + v.y*wr.y + v.z*wr.z + v.w*wr.w;
        s2 += v.x*wo.x + v.y*wo.y + v.z*wo.z + v.w*wo.w;
    }
#pragma unroll
    for (int o = 16; o; o >>= 1) {
        s1 += __shfl_down_sync(0xFFFFFFFFu, s1, o);
        s2 += __shfl_down_sync(0xFFFFFFFFu, s2, o);
    }
    if (lane == 0) { rrel[w] = s1; rroot[w] = s2; }
}

// scalar segment-sum of rrel[src] into sseg[tgt]
__global__ void escore_kernel(const int* __restrict__ src, const int* __restrict__ tgt,
                              const float* __restrict__ rrel, float* __restrict__ sseg, int nedges)
{
    int e = blockIdx.x * blockDim.x + threadIdx.x;
    if (e >= nedges) return;
    int s = src[e];
    if (s < 0) return;
    atomicAdd(&sseg[tgt[e]], rrel[s]);
}

// per-graph top-K via bitonic sort of (score,idx) keys; set-invariant ordering
template<int NPGT, int KSEL>
__global__ void topk_kernel(const float* __restrict__ sseg, const float* __restrict__ rroot,
                            const float* __restrict__ brel,
                            int* __restrict__ perm, float* __restrict__ tanhv,
                            int* __restrict__ mapping)
{
    __shared__ unsigned long long keys[NPGT];
    int g = blockIdx.x, tid = threadIdx.x;
    float br = brel[0];
    for (int i = tid; i < NPGT; i += blockDim.x) {
        int node = g * NPGT + i;
        float sc = sseg[node] + br + rroot[node];
        unsigned u = __float_as_uint(sc);
        u = (u & 0x80000000u) ? ~u : (u | 0x80000000u);
        keys[i] = ((unsigned long long)u << 32) | (unsigned)i;
    }
    __syncthreads();
    for (int k = 2; k <= NPGT; k <<= 1) {
        for (int j = k >> 1; j > 0; j >>= 1) {
            for (int t = tid; t < NPGT; t += blockDim.x) {
                int ixj = t ^ j;
                if (ixj > t) {
                    unsigned long long a = keys[t], c = keys[ixj];
                    bool desc = ((t & k) == 0);
                    if ((a < c) == desc) { keys[t] = c; keys[ixj] = a; }
                }
            }
            __syncthreads();
        }
    }
    for (int t = tid; t < KSEL; t += blockDim.x) {
        int li = (int)(keys[t] & 0xFFFFFFFFull);
        int node = g * NPGT + li;
        float sc = sseg[node] + br + rroot[node];
        int ni = g * KSEL + t;
        perm[ni]  = node;
        tanhv[ni] = tanhf(sc);
        if (mapping) mapping[node] = ni;
    }
}

// gather + BN/ReLU + tanh-scale (float4)
__global__ void gather_kernel(const float* __restrict__ pre, const int* __restrict__ perm,
                              const float* __restrict__ scale, const float* __restrict__ shift,
                              const float* __restrict__ tv, float* __restrict__ o, int n)
{
    const int V = H1 / 4;  // 32
    int i = blockIdx.x * blockDim.x + threadIdx.x;
    if (i >= n * V) return;
    int node = i / V, off = i - node * V;
    float4 v  = reinterpret_cast<const float4*>(pre)[(size_t)perm[node] * V + off];
    float4 sc = reinterpret_cast<const float4*>(scale)[off];
    float4 sh = reinterpret_cast<const float4*>(shift)[off];
    float t = tv[node];
    v.x = fmaxf(fmaf(v.x, sc.x, sh.x), 0.f) * t;
    v.y = fmaxf(fmaf(v.y, sc.y, sh.y), 0.f) * t;
    v.z = fmaxf(fmaf(v.z, sc.z, sh.z), 0.f) * t;
    v.w = fmaxf(fmaf(v.w, sc.w, sh.w), 0.f) * t;
    reinterpret_cast<float4*>(o)[i] = v;
}

__global__ void remap_kernel(const int* __restrict__ src, const int* __restrict__ tgt,
                             const int* __restrict__ mapping,
                             int* __restrict__ src2, int* __restrict__ tgt2)
{
    int e = blockIdx.x * blockDim.x + threadIdx.x;
    if (e >= Ee) return;
    int s = mapping[src[e]];
    int t = mapping[tgt[e]];
    if (s < 0 || t < 0) { s = -1; t = -1; }
    src2[e] = s; tgt2[e] = t;
}

// per-graph: BN/ReLU on the fly -> pooled mean -> relu -> 256x2 linear -> softmax
__global__ void final_kernel(const float* __restrict__ pre2, const int* __restrict__ perm2,
                             const float* __restrict__ scale, const float* __restrict__ shift,
                             const float* __restrict__ tanhv2, const float* __restrict__ Wlin,
                             const float* __restrict__ blin, float* __restrict__ outp)
{
    int g = blockIdx.x, c = threadIdx.x;   // 256 threads
    __shared__ int   sp[K2];
    __shared__ float st[K2];
    for (int i = c; i < K2; i += 256) { sp[i] = perm2[g * K2 + i]; st[i] = tanhv2[g * K2 + i]; }
    __syncthreads();
    float sc = scale[c], sh = shift[c];
    float acc = 0.f;
#pragma unroll 4
    for (int r = 0; r < K2; r++)
        acc += fmaxf(fmaf(pre2[(size_t)sp[r] * H2 + c], sc, sh), 0.f) * st[r];
    float p = fmaxf(acc * (1.0f / (float)K2), 0.f);
    __shared__ float red0[256], red1[256];
    red0[c] = p * Wlin[c * 2 + 0];
    red1[c] = p * Wlin[c * 2 + 1];
    __syncthreads();
    for (int s = 128; s; s >>= 1) {
        if (c < s) { red0[c] += red0[c + s]; red1[c] += red1[c + s]; }
        __syncthreads();
    }
    if (c == 0) {
        float a = red0[0] + blin[0];
        float b = red1[0] + blin[1];
        float m = fmaxf(a, b);
        float ea = expf(a - m), eb = expf(b - m);
        float inv = 1.f / (ea + eb);
        outp[g * 2 + 0] = ea * inv;
        outp[g * 2 + 1] = eb * inv;
    }
}

// ---------------- host launch ----------------
template <typename T>
static void* symaddr(const T& s) { void* p = nullptr; cudaGetSymbolAddress(&p, s); return p; }

extern "C" void kernel_launch(void* const* d_in, const int* in_sizes, int n_in,
                              void* d_out, int out_size)
{
    const float* x     = (const float*)d_in[0];
    const int*   ei    = (const int*)  d_in[1];
    const int*   src   = ei;
    const int*   tgt   = ei + Ee;
    const float* W1l   = (const float*)d_in[3];
    const float* b1l   = (const float*)d_in[4];
    const float* W1r   = (const float*)d_in[5];
    const float* bn1g  = (const float*)d_in[6];
    const float* bn1b  = (const float*)d_in[7];
    const float* p1Wrel  = (const float*)d_in[8];
    const float* p1brel  = (const float*)d_in[9];
    const float* p1Wroot = (const float*)d_in[10];
    const float* W2l   = (const float*)d_in[11];
    const float* b2l   = (const float*)d_in[12];
    const float* W2r   = (const float*)d_in[13];
    const float* bn2g  = (const float*)d_in[14];
    const float* bn2b  = (const float*)d_in[15];
    const float* p2Wrel  = (const float*)d_in[16];
    const float* p2brel  = (const float*)d_in[17];
    const float* p2Wroot = (const float*)d_in[18];
    const float* Wlin  = (const float*)d_in[19];
    const float* blin  = (const float*)d_in[20];
    float* out = (float*)d_out;

    float* z1    = (float*)symaddr(g_z1);
    float* agg1  = z1;
    float* cnt1  = z1 + Nn*IND;
    float* sseg1 = cnt1 + Nn;
    float* bnacc1= sseg1 + Nn;
    float* z2    = (float*)symaddr(g_z2);
    float* agg2  = z2;
    float* cnt2  = z2 + N1*H1;
    float* sseg2 = cnt2 + N1;
    float* bnacc2= sseg2 + N1;

    float* rrel1 = (float*)symaddr(g_rrel1);
    float* rroot1= (float*)symaddr(g_rroot1);
    float* pre1  = (float*)symaddr(g_pre1);
    int*   map1  = (int*)  symaddr(g_map1);
    int*   perm1 = (int*)  symaddr(g_perm1);
    float* tanh1 = (float*)symaddr(g_tanh1);
    int*   src2  = (int*)  symaddr(g_src2);
    int*   tgt2  = (int*)  symaddr(g_tgt2);
    float* h1new = (float*)symaddr(g_h1new);
    float* rrel2 = (float*)symaddr(g_rrel2);
    float* rroot2= (float*)symaddr(g_rroot2);
    float* pre2  = (float*)symaddr(g_pre2);
    int*   perm2 = (int*)  symaddr(g_perm2);
    float* tanh2 = (float*)symaddr(g_tanh2);
    float* scale = (float*)symaddr(g_scale);
    float* shift = (float*)symaddr(g_shift);
    int*   ctr1  = (int*)  symaddr(g_ctr1);
    int*   ctr2  = (int*)  symaddr(g_ctr2);

    const int SMEM = (32*256 + 32*(256+4)) * 4 > (32*128 + 32*(256+4))*4
                   ? 49664 : 49664;  // both configs: 49664 B
    static bool attr_set = false;
    if (!attr_set) {
        cudaFuncSetAttribute((const void*)gemm_dual3<IND, H1, 16>,
                             cudaFuncAttributeMaxDynamicSharedMemorySize, SMEM);
        cudaFuncSetAttribute((const void*)gemm_dual3<H1, H2, 32>,
                             cudaFuncAttributeMaxDynamicSharedMemorySize, SMEM);
        attr_set = true;
    }

    // ---- zero-fill (all up front) ----
    cudaMemsetAsync(z1, 0, sizeof(float)*Z1_FLOATS);
    cudaMemsetAsync(z2, 0, sizeof(float)*Z2_FLOATS);
    cudaMemsetAsync(map1, 0xFF, sizeof(int)*Nn);   // -1

    // ---- stage 1 ----
    agg_kernel<IND><<<(Ee*(IND/4))/256, 256>>>(src, tgt, x, agg1, cnt1, Ee);
    {
        // CG=16 -> NTY=16, BM=256; smem = (32*128 + 32*260)*4 = 49664
        gemm_dual3<IND, H1, 16><<<Nn/256, 256, 49664>>>(
            agg1, cnt1, x, W1l, W1r, b1l, pre1,
            bnacc1, ctr1, bn1g, bn1b, scale, shift, 1.f/(float)Nn);
    }
    bnad_kernel<H1><<<Nn/8, 256>>>(pre1, scale, shift, p1Wrel, p1Wroot, rrel1, rroot1, Nn);
    escore_kernel<<<Ee/256, 256>>>(src, tgt, rrel1, sseg1, Ee);
    topk_kernel<NPG, K1><<<Bg, 1024>>>(sseg1, rroot1, p1brel, perm1, tanh1, map1);
    gather_kernel<<<(N1*(H1/4))/256, 256>>>(pre1, perm1, scale, shift, tanh1, h1new, N1);
    remap_kernel<<<Ee/256, 256>>>(src, tgt, map1, src2, tgt2);

    // ---- stage 2 ----
    agg_kernel<H1><<<(Ee*(H1/4))/256, 256>>>(src2, tgt2, h1new, agg2, cnt2, Ee);
    {
        // CG=32 -> NTY=8, BM=128; smem = (32*256 + 32*132)*4 = 49664
        gemm_dual3<H1, H2, 32><<<N1/128, 256, 49664>>>(
            agg2, cnt2, h1new, W2l, W2r, b2l, pre2,
            bnacc2, ctr2, bn2g, bn2b, scale, shift, 1.f/(float)N1);
    }
    bnad_kernel<H2><<<N1/8, 256>>>(pre2, scale, shift, p2Wrel, p2Wroot, rrel2, rroot2, N1);
    escore_kernel<<<Ee/256, 256>>>(src2, tgt2, rrel2, sseg2, Ee);
    topk_kernel<K1, K2><<<Bg, 1024>>>(sseg2, rroot2, p2brel, perm2, tanh2, nullptr);

    // ---- readout ----
    final_kernel<<<Bg, 256>>>(pre2, perm2, scale, shift, tanh2, Wlin, blin, out);

    (void)in_sizes; (void)n_in; (void)out_size;
}

// round 4
// speedup vs baseline: 1.2238x; 1.2238x over previous
#include <cuda_runtime.h>
#include <math.h>

// ---------------- problem constants ----------------
#define Bg   32
#define NPG  2048
#define Nn   (Bg*NPG)        // 65536
#define Ee   (Nn*8)          // 524288
#define IND  64
#define H1   128
#define H2   256
#define K1   1024
#define K2   512
#define N1   (Bg*K1)         // 32768
#define N2   (Bg*K2)         // 16384

// ---------------- scratch (device globals; no allocs) ----------------
#define Z1_FLOATS (Nn*IND + Nn + Nn + 2*H1)
__device__ float g_z1[Z1_FLOATS];    // [agg1 | cnt1 | sseg1 | bnacc1]
#define Z2_FLOATS (N1*H1 + N1 + N1 + 2*H2)
__device__ float g_z2[Z2_FLOATS];    // [agg2 | cnt2 | sseg2 | bnacc2]

__device__ float g_rrel1[Nn];
__device__ float g_rroot1[Nn];
__device__ float g_pre1 [Nn*H1];
__device__ int   g_map1 [Nn];
__device__ int   g_perm1[N1];
__device__ float g_tanh1[N1];
__device__ int   g_src2 [Ee];
__device__ int   g_tgt2 [Ee];
__device__ float g_h1new[N1*H1];
__device__ float g_rrel2[N1];
__device__ float g_rroot2[N1];
__device__ float g_pre2 [N1*H2];
__device__ int   g_perm2[N2];
__device__ float g_tanh2[N2];
__device__ float g_scale[H2];
__device__ float g_shift[H2];
__device__ int   g_ctr1 = 0;
__device__ int   g_ctr2 = 0;

// ---------------- f32x2 helpers ----------------
__device__ __forceinline__ unsigned long long pk2(float lo, float hi) {
    unsigned long long r;
    asm("mov.b64 %0, {%1,%2};" : "=l"(r) : "f"(lo), "f"(hi));
    return r;
}
__device__ __forceinline__ void upk2(unsigned long long v, float& lo, float& hi) {
    asm("mov.b64 {%0,%1}, %2;" : "=f"(lo), "=f"(hi) : "l"(v));
}
__device__ __forceinline__ void ffma2(unsigned long long& d, unsigned long long a, unsigned long long b) {
    asm("fma.rn.f32x2 %0, %1, %2, %0;" : "+l"(d) : "l"(a), "l"(b));
}

// ---------------- kernels ----------------

// vectorized mean aggregation over edges: one thread per (edge, float4)
template<int D>
__global__ void agg_kernel(const int* __restrict__ src, const int* __restrict__ tgt,
                           const float* __restrict__ xin, float* __restrict__ aggo,
                           float* __restrict__ cnt, int nedges)
{
    const int V = D / 4;
    int i = blockIdx.x * blockDim.x + threadIdx.x;
    if (i >= nedges * V) return;
    int e  = i / V;
    int f4 = i - e * V;
    int s = src[e];
    if (s < 0) return;
    int t = tgt[e];
    float4 v = reinterpret_cast<const float4*>(xin)[(size_t)s * V + f4];
    asm volatile("red.global.add.v4.f32 [%0], {%1,%2,%3,%4};"
                 :: "l"(&aggo[(size_t)t * D + f4 * 4]),
                    "f"(v.x), "f"(v.y), "f"(v.z), "f"(v.w) : "memory");
    if (f4 == 0) atomicAdd(&cnt[t], 1.0f);
}

// pre[n,OD] = (agg[n]/max(cnt,1)) @ Wl + xin @ Wr + bias   (K concat, FFMA2)
// 256 threads; CG column-groups of TN=8 cols; 8 rows per thread (4 row-pairs).
// Epilogue: per-column sum/sumsq into bnacc; last block computes scale/shift.
template<int KD, int OD, int BM, int CG>
__global__ void __launch_bounds__(256)
gemm_dual4(const float* __restrict__ agg, const float* __restrict__ cnt,
           const float* __restrict__ xin,
           const float* __restrict__ Wl, const float* __restrict__ Wr,
           const float* __restrict__ bias, float* __restrict__ outp,
           float* __restrict__ bnacc, int* __restrict__ ctr,
           const float* __restrict__ bng, const float* __restrict__ bnb,
           float* __restrict__ scale, float* __restrict__ shift,
           float invn)
{
    const int TN = 8, BK = 32, ASTR = BM + 4;
    const int NTY = 256 / CG;   // = BM/8
    extern __shared__ float sh[];
    float* sW = sh;             // BK*OD
    float* sA = sh + BK * OD;   // BK*ASTR

    int tid = threadIdx.x;
    int tx  = tid % CG;
    int ty  = tid / CG;
    int row0 = blockIdx.x * BM;

    unsigned long long acc[4][TN];
#pragma unroll
    for (int r = 0; r < 4; r++)
#pragma unroll
        for (int j = 0; j < TN; j++) acc[r][j] = 0ull;

    for (int kt = 0; kt < 2 * KD; kt += BK) {
        for (int i = tid; i < BK * OD; i += 256) {
            int k = i / OD, c = i - k * OD;
            int kg = kt + k;
            sW[i] = (kg < KD) ? Wl[(size_t)kg * OD + c] : Wr[(size_t)(kg - KD) * OD + c];
        }
        for (int i = tid; i < BM * BK; i += 256) {
            int m = i >> 5, k = i & 31;
            int kg = kt + k;
            int row = row0 + m;
            float v;
            if (kg < KD) v = agg[(size_t)row * KD + kg] * (1.f / fmaxf(cnt[row], 1.f));
            else         v = xin[(size_t)row * KD + (kg - KD)];
            sA[k * ASTR + m] = v;
        }
        __syncthreads();
#pragma unroll
        for (int k = 0; k < BK; k++) {
            const float4 a0 = *reinterpret_cast<const float4*>(&sA[k * ASTR + ty * 8]);
            const float4 a1 = *reinterpret_cast<const float4*>(&sA[k * ASTR + ty * 8 + 4]);
            unsigned long long ap[4] = { pk2(a0.x, a0.y), pk2(a0.z, a0.w),
                                         pk2(a1.x, a1.y), pk2(a1.z, a1.w) };
#pragma unroll
            for (int jj = 0; jj < TN / 4; jj++) {
                float4 w4 = *reinterpret_cast<const float4*>(&sW[k * OD + tx * TN + jj * 4]);
                unsigned long long w0 = pk2(w4.x, w4.x), w1 = pk2(w4.y, w4.y);
                unsigned long long w2 = pk2(w4.z, w4.z), w3 = pk2(w4.w, w4.w);
#pragma unroll
                for (int r = 0; r < 4; r++) {
                    ffma2(acc[r][jj*4+0], ap[r], w0);
                    ffma2(acc[r][jj*4+1], ap[r], w1);
                    ffma2(acc[r][jj*4+2], ap[r], w2);
                    ffma2(acc[r][jj*4+3], ap[r], w3);
                }
            }
        }
        __syncthreads();
    }

    // epilogue: unpack, add bias, store; accumulate column stats
    float cs[TN], cs2[TN];
#pragma unroll
    for (int j = 0; j < TN; j++) { cs[j] = 0.f; cs2[j] = 0.f; }
    float bb[TN];
#pragma unroll
    for (int jj = 0; jj < TN / 4; jj++) {
        float4 b4 = *reinterpret_cast<const float4*>(&bias[tx * TN + jj * 4]);
        bb[jj*4+0]=b4.x; bb[jj*4+1]=b4.y; bb[jj*4+2]=b4.z; bb[jj*4+3]=b4.w;
    }
#pragma unroll
    for (int r = 0; r < 4; r++) {
        float lo[TN], hi[TN];
#pragma unroll
        for (int j = 0; j < TN; j++) {
            upk2(acc[r][j], lo[j], hi[j]);
            lo[j] += bb[j]; hi[j] += bb[j];
            cs[j]  += lo[j] + hi[j];
            cs2[j] += lo[j]*lo[j] + hi[j]*hi[j];
        }
        int row_lo = row0 + ty * 8 + 2 * r;
#pragma unroll
        for (int jj = 0; jj < TN / 4; jj++) {
            int c = tx * TN + jj * 4;
            *reinterpret_cast<float4*>(&outp[(size_t)row_lo * OD + c]) =
                make_float4(lo[jj*4], lo[jj*4+1], lo[jj*4+2], lo[jj*4+3]);
            *reinterpret_cast<float4*>(&outp[(size_t)(row_lo+1) * OD + c]) =
                make_float4(hi[jj*4], hi[jj*4+1], hi[jj*4+2], hi[jj*4+3]);
        }
    }

    // block-level stats reduce (reuse smem), then one atomic per column
    __syncthreads();
    float* sRed = sh;   // NTY*OD floats (<= 8KB)
#pragma unroll
    for (int j = 0; j < TN; j++) sRed[ty * OD + tx * TN + j] = cs[j];
    __syncthreads();
    for (int c = tid; c < OD; c += 256) {
        float t = 0.f;
#pragma unroll
        for (int i = 0; i < NTY; i++) t += sRed[i * OD + c];
        atomicAdd(&bnacc[c], t);
    }
    __syncthreads();
#pragma unroll
    for (int j = 0; j < TN; j++) sRed[ty * OD + tx * TN + j] = cs2[j];
    __syncthreads();
    for (int c = tid; c < OD; c += 256) {
        float t = 0.f;
#pragma unroll
        for (int i = 0; i < NTY; i++) t += sRed[i * OD + c];
        atomicAdd(&bnacc[OD + c], t);
    }

    // last block computes BN scale/shift
    __shared__ int sDone;
    __threadfence();
    if (tid == 0) {
        int old = atomicAdd(ctr, 1);
        sDone = (old == (int)gridDim.x - 1);
    }
    __syncthreads();
    if (sDone) {
        if (tid < OD) {
            float s  = __ldcg(&bnacc[tid]);
            float s2 = __ldcg(&bnacc[OD + tid]);
            float m   = s * invn;
            float var = s2 * invn - m * m;
            float sc  = rsqrtf(var + 1e-5f) * bng[tid];
            scale[tid] = sc;
            shift[tid] = bnb[tid] - m * sc;
        }
        if (tid == 0) *ctr = 0;
    }
}

// fused: BN apply (registers only) + ReLU + two score dot products. One warp per row.
template<int D>
__global__ void bnad_kernel(const float* __restrict__ pre, const float* __restrict__ scale,
                            const float* __restrict__ shift,
                            const float* __restrict__ wrel, const float* __restrict__ wroot,
                            float* __restrict__ rrel, float* __restrict__ rroot, int nrows)
{
    int w = (blockIdx.x * blockDim.x + threadIdx.x) >> 5;
    int lane = threadIdx.x & 31;
    if (w >= nrows) return;
    const int V = D / 128;
    float s1 = 0.f, s2 = 0.f;
    const float4* rowp = reinterpret_cast<const float4*>(pre + (size_t)w * D);
#pragma unroll
    for (int q = 0; q < V; q++) {
        int c4 = lane + q * 32;
        float4 v  = rowp[c4];
        float4 sc = reinterpret_cast<const float4*>(scale)[c4];
        float4 sh = reinterpret_cast<const float4*>(shift)[c4];
        v.x = fmaxf(fmaf(v.x, sc.x, sh.x), 0.f);
        v.y = fmaxf(fmaf(v.y, sc.y, sh.y), 0.f);
        v.z = fmaxf(fmaf(v.z, sc.z, sh.z), 0.f);
        v.w = fmaxf(fmaf(v.w, sc.w, sh.w), 0.f);
        float4 wr = reinterpret_cast<const float4*>(wrel)[c4];
        float4 wo = reinterpret_cast<const float4*>(wroot)[c4];
        s1 += v.x*wr.x + v.y*wr.y + v.z*wr.z + v.w*wr.w;
        s2 += v.x*wo.x + v.y*wo.y + v.z*wo.z + v.w*wo.w;
    }
#pragma unroll
    for (int o = 16; o; o >>= 1) {
        s1 += __shfl_down_sync(0xFFFFFFFFu, s1, o);
        s2 += __shfl_down_sync(0xFFFFFFFFu, s2, o);
    }
    if (lane == 0) { rrel[w] = s1; rroot[w] = s2; }
}

// scalar segment-sum of rrel[src] into sseg[tgt]
__global__ void escore_kernel(const int* __restrict__ src, const int* __restrict__ tgt,
                              const float* __restrict__ rrel, float* __restrict__ sseg, int nedges)
{
    int e = blockIdx.x * blockDim.x + threadIdx.x;
    if (e >= nedges) return;
    int s = src[e];
    if (s < 0) return;
    atomicAdd(&sseg[tgt[e]], rrel[s]);
}

// per-graph top-K via bitonic sort of (score,idx) keys; set-invariant ordering
template<int NPGT, int KSEL>
__global__ void topk_kernel(const float* __restrict__ sseg, const float* __restrict__ rroot,
                            const float* __restrict__ brel,
                            int* __restrict__ perm, float* __restrict__ tanhv,
                            int* __restrict__ mapping)
{
    __shared__ unsigned long long keys[NPGT];
    int g = blockIdx.x, tid = threadIdx.x;
    float br = brel[0];
    for (int i = tid; i < NPGT; i += blockDim.x) {
        int node = g * NPGT + i;
        float sc = sseg[node] + br + rroot[node];
        unsigned u = __float_as_uint(sc);
        u = (u & 0x80000000u) ? ~u : (u | 0x80000000u);
        keys[i] = ((unsigned long long)u << 32) | (unsigned)i;
    }
    __syncthreads();
    for (int k = 2; k <= NPGT; k <<= 1) {
        for (int j = k >> 1; j > 0; j >>= 1) {
            for (int t = tid; t < NPGT; t += blockDim.x) {
                int ixj = t ^ j;
                if (ixj > t) {
                    unsigned long long a = keys[t], c = keys[ixj];
                    bool desc = ((t & k) == 0);
                    if ((a < c) == desc) { keys[t] = c; keys[ixj] = a; }
                }
            }
            __syncthreads();
        }
    }
    for (int t = tid; t < KSEL; t += blockDim.x) {
        int li = (int)(keys[t] & 0xFFFFFFFFull);
        int node = g * NPGT + li;
        float sc = sseg[node] + br + rroot[node];
        int ni = g * KSEL + t;
        perm[ni]  = node;
        tanhv[ni] = tanhf(sc);
        if (mapping) mapping[node] = ni;
    }
}

// gather + BN/ReLU + tanh-scale (float4)
__global__ void gather_kernel(const float* __restrict__ pre, const int* __restrict__ perm,
                              const float* __restrict__ scale, const float* __restrict__ shift,
                              const float* __restrict__ tv, float* __restrict__ o, int n)
{
    const int V = H1 / 4;  // 32
    int i = blockIdx.x * blockDim.x + threadIdx.x;
    if (i >= n * V) return;
    int node = i / V, off = i - node * V;
    float4 v  = reinterpret_cast<const float4*>(pre)[(size_t)perm[node] * V + off];
    float4 sc = reinterpret_cast<const float4*>(scale)[off];
    float4 sh = reinterpret_cast<const float4*>(shift)[off];
    float t = tv[node];
    v.x = fmaxf(fmaf(v.x, sc.x, sh.x), 0.f) * t;
    v.y = fmaxf(fmaf(v.y, sc.y, sh.y), 0.f) * t;
    v.z = fmaxf(fmaf(v.z, sc.z, sh.z), 0.f) * t;
    v.w = fmaxf(fmaf(v.w, sc.w, sh.w), 0.f) * t;
    reinterpret_cast<float4*>(o)[i] = v;
}

__global__ void remap_kernel(const int* __restrict__ src, const int* __restrict__ tgt,
                             const int* __restrict__ mapping,
                             int* __restrict__ src2, int* __restrict__ tgt2)
{
    int e = blockIdx.x * blockDim.x + threadIdx.x;
    if (e >= Ee) return;
    int s = mapping[src[e]];
    int t = mapping[tgt[e]];
    if (s < 0 || t < 0) { s = -1; t = -1; }
    src2[e] = s; tgt2[e] = t;
}

// per-graph: BN/ReLU on the fly -> pooled mean -> relu -> 256x2 linear -> softmax
__global__ void final_kernel(const float* __restrict__ pre2, const int* __restrict__ perm2,
                             const float* __restrict__ scale, const float* __restrict__ shift,
                             const float* __restrict__ tanhv2, const float* __restrict__ Wlin,
                             const float* __restrict__ blin, float* __restrict__ outp)
{
    int g = blockIdx.x, c = threadIdx.x;   // 256 threads
    __shared__ int   sp[K2];
    __shared__ float st[K2];
    for (int i = c; i < K2; i += 256) { sp[i] = perm2[g * K2 + i]; st[i] = tanhv2[g * K2 + i]; }
    __syncthreads();
    float sc = scale[c], sh = shift[c];
    float acc = 0.f;
#pragma unroll 4
    for (int r = 0; r < K2; r++)
        acc += fmaxf(fmaf(pre2[(size_t)sp[r] * H2 + c], sc, sh), 0.f) * st[r];
    float p = fmaxf(acc * (1.0f / (float)K2), 0.f);
    __shared__ float red0[256], red1[256];
    red0[c] = p * Wlin[c * 2 + 0];
    red1[c] = p * Wlin[c * 2 + 1];
    __syncthreads();
    for (int s = 128; s; s >>= 1) {
        if (c < s) { red0[c] += red0[c + s]; red1[c] += red1[c + s]; }
        __syncthreads();
    }
    if (c == 0) {
        float a = red0[0] + blin[0];
        float b = red1[0] + blin[1];
        float m = fmaxf(a, b);
        float ea = expf(a - m), eb = expf(b - m);
        float inv = 1.f / (ea + eb);
        outp[g * 2 + 0] = ea * inv;
        outp[g * 2 + 1] = eb * inv;
    }
}

// ---------------- host launch ----------------
template <typename T>
static void* symaddr(const T& s) { void* p = nullptr; cudaGetSymbolAddress(&p, s); return p; }

extern "C" void kernel_launch(void* const* d_in, const int* in_sizes, int n_in,
                              void* d_out, int out_size)
{
    const float* x     = (const float*)d_in[0];
    const int*   ei    = (const int*)  d_in[1];
    const int*   src   = ei;
    const int*   tgt   = ei + Ee;
    const float* W1l   = (const float*)d_in[3];
    const float* b1l   = (const float*)d_in[4];
    const float* W1r   = (const float*)d_in[5];
    const float* bn1g  = (const float*)d_in[6];
    const float* bn1b  = (const float*)d_in[7];
    const float* p1Wrel  = (const float*)d_in[8];
    const float* p1brel  = (const float*)d_in[9];
    const float* p1Wroot = (const float*)d_in[10];
    const float* W2l   = (const float*)d_in[11];
    const float* b2l   = (const float*)d_in[12];
    const float* W2r   = (const float*)d_in[13];
    const float* bn2g  = (const float*)d_in[14];
    const float* bn2b  = (const float*)d_in[15];
    const float* p2Wrel  = (const float*)d_in[16];
    const float* p2brel  = (const float*)d_in[17];
    const float* p2Wroot = (const float*)d_in[18];
    const float* Wlin  = (const float*)d_in[19];
    const float* blin  = (const float*)d_in[20];
    float* out = (float*)d_out;

    float* z1    = (float*)symaddr(g_z1);
    float* agg1  = z1;
    float* cnt1  = z1 + Nn*IND;
    float* sseg1 = cnt1 + Nn;
    float* bnacc1= sseg1 + Nn;
    float* z2    = (float*)symaddr(g_z2);
    float* agg2  = z2;
    float* cnt2  = z2 + N1*H1;
    float* sseg2 = cnt2 + N1;
    float* bnacc2= sseg2 + N1;

    float* rrel1 = (float*)symaddr(g_rrel1);
    float* rroot1= (float*)symaddr(g_rroot1);
    float* pre1  = (float*)symaddr(g_pre1);
    int*   map1  = (int*)  symaddr(g_map1);
    int*   perm1 = (int*)  symaddr(g_perm1);
    float* tanh1 = (float*)symaddr(g_tanh1);
    int*   src2  = (int*)  symaddr(g_src2);
    int*   tgt2  = (int*)  symaddr(g_tgt2);
    float* h1new = (float*)symaddr(g_h1new);
    float* rrel2 = (float*)symaddr(g_rrel2);
    float* rroot2= (float*)symaddr(g_rroot2);
    float* pre2  = (float*)symaddr(g_pre2);
    int*   perm2 = (int*)  symaddr(g_perm2);
    float* tanh2 = (float*)symaddr(g_tanh2);
    float* scale = (float*)symaddr(g_scale);
    float* shift = (float*)symaddr(g_shift);
    int*   ctr1  = (int*)  symaddr(g_ctr1);
    int*   ctr2  = (int*)  symaddr(g_ctr2);

    // smem: stage1 (32*128 + 32*132)*4 = 33280 ; stage2 (32*256 + 32*68)*4 = 41472
    static bool attr_set = false;
    if (!attr_set) {
        cudaFuncSetAttribute((const void*)gemm_dual4<IND, H1, 128, 16>,
                             cudaFuncAttributeMaxDynamicSharedMemorySize, 33280);
        cudaFuncSetAttribute((const void*)gemm_dual4<H1, H2, 64, 32>,
                             cudaFuncAttributeMaxDynamicSharedMemorySize, 41472);
        attr_set = true;
    }

    // ---- zero-fill (all up front) ----
    cudaMemsetAsync(z1, 0, sizeof(float)*Z1_FLOATS);
    cudaMemsetAsync(z2, 0, sizeof(float)*Z2_FLOATS);
    cudaMemsetAsync(map1, 0xFF, sizeof(int)*Nn);   // -1

    // ---- stage 1 ----
    agg_kernel<IND><<<(Ee*(IND/4))/256, 256>>>(src, tgt, x, agg1, cnt1, Ee);
    gemm_dual4<IND, H1, 128, 16><<<Nn/128, 256, 33280>>>(
        agg1, cnt1, x, W1l, W1r, b1l, pre1,
        bnacc1, ctr1, bn1g, bn1b, scale, shift, 1.f/(float)Nn);
    bnad_kernel<H1><<<Nn/8, 256>>>(pre1, scale, shift, p1Wrel, p1Wroot, rrel1, rroot1, Nn);
    escore_kernel<<<Ee/256, 256>>>(src, tgt, rrel1, sseg1, Ee);
    topk_kernel<NPG, K1><<<Bg, 1024>>>(sseg1, rroot1, p1brel, perm1, tanh1, map1);
    gather_kernel<<<(N1*(H1/4))/256, 256>>>(pre1, perm1, scale, shift, tanh1, h1new, N1);
    remap_kernel<<<Ee/256, 256>>>(src, tgt, map1, src2, tgt2);

    // ---- stage 2 ----
    agg_kernel<H1><<<(Ee*(H1/4))/256, 256>>>(src2, tgt2, h1new, agg2, cnt2, Ee);
    gemm_dual4<H1, H2, 64, 32><<<N1/64, 256, 41472>>>(
        agg2, cnt2, h1new, W2l, W2r, b2l, pre2,
        bnacc2, ctr2, bn2g, bn2b, scale, shift, 1.f/(float)N1);
    bnad_kernel<H2><<<N1/8, 256>>>(pre2, scale, shift, p2Wrel, p2Wroot, rrel2, rroot2, N1);
    escore_kernel<<<Ee/256, 256>>>(src2, tgt2, rrel2, sseg2, Ee);
    topk_kernel<K1, K2><<<Bg, 1024>>>(sseg2, rroot2, p2brel, perm2, tanh2, nullptr);

    // ---- readout ----
    final_kernel<<<Bg, 256>>>(pre2, perm2, scale, shift, tanh2, Wlin, blin, out);

    (void)in_sizes; (void)n_in; (void)out_size;
}

// round 5
// speedup vs baseline: 1.3629x; 1.1137x over previous
#include <cuda_runtime.h>
#include <math.h>

// ---------------- problem constants ----------------
#define Bg   32
#define NPG  2048
#define Nn   (Bg*NPG)        // 65536
#define Ee   (Nn*8)          // 524288
#define IND  64
#define H1   128
#define H2   256
#define K1   1024
#define K2   512
#define N1   (Bg*K1)         // 32768
#define N2   (Bg*K2)         // 16384

// ---------------- scratch (device globals; no allocs) ----------------
#define Z1_FLOATS (Nn*IND + Nn + Nn + 2*H1)
__device__ float g_z1[Z1_FLOATS];    // [agg1 | cnt1 | sseg1 | bnacc1]
#define Z2_FLOATS (N1*H1 + N1 + N1 + 2*H2)
__device__ float g_z2[Z2_FLOATS];    // [agg2 | cnt2 | sseg2 | bnacc2]

__device__ float g_rrel1[Nn];
__device__ float g_rroot1[Nn];
__device__ float g_pre1 [Nn*H1];
__device__ int   g_map1 [Nn];
__device__ int   g_perm1[N1];
__device__ float g_tanh1[N1];
__device__ int   g_src2 [Ee];
__device__ int   g_tgt2 [Ee];
__device__ float g_h1new[N1*H1];
__device__ float g_rrel2[N1];
__device__ float g_rroot2[N1];
__device__ float g_pre2 [N1*H2];
__device__ int   g_perm2[N2];
__device__ float g_tanh2[N2];
__device__ float g_scale[H2];
__device__ float g_shift[H2];
__device__ int   g_ctr1 = 0;
__device__ int   g_ctr2 = 0;

// ---------------- helpers ----------------
__device__ __forceinline__ unsigned long long pk2(float lo, float hi) {
    unsigned long long r;
    asm("mov.b64 %0, {%1,%2};" : "=l"(r) : "f"(lo), "f"(hi));
    return r;
}
__device__ __forceinline__ void upk2(unsigned long long v, float& lo, float& hi) {
    asm("mov.b64 {%0,%1}, %2;" : "=f"(lo), "=f"(hi) : "l"(v));
}
__device__ __forceinline__ void ffma2(unsigned long long& d, unsigned long long a, unsigned long long b) {
    asm("fma.rn.f32x2 %0, %1, %2, %0;" : "+l"(d) : "l"(a), "l"(b));
}
__device__ __forceinline__ void cp_async16(float* smem, const float* gmem) {
    unsigned saddr = (unsigned)__cvta_generic_to_shared(smem);
    asm volatile("cp.async.cg.shared.global [%0], [%1], 16;" :: "r"(saddr), "l"(gmem) : "memory");
}

// ---------------- kernels ----------------

// vectorized mean aggregation over edges: one thread per (edge, float4)
template<int D>
__global__ void agg_kernel(const int* __restrict__ src, const int* __restrict__ tgt,
                           const float* __restrict__ xin, float* __restrict__ aggo,
                           float* __restrict__ cnt, int nedges)
{
    const int V = D / 4;
    int i = blockIdx.x * blockDim.x + threadIdx.x;
    if (i >= nedges * V) return;
    int e  = i / V;
    int f4 = i - e * V;
    int s = src[e];
    if (s < 0) return;
    int t = tgt[e];
    float4 v = reinterpret_cast<const float4*>(xin)[(size_t)s * V + f4];
    asm volatile("red.global.add.v4.f32 [%0], {%1,%2,%3,%4};"
                 :: "l"(&aggo[(size_t)t * D + f4 * 4]),
                    "f"(v.x), "f"(v.y), "f"(v.z), "f"(v.w) : "memory");
    if (f4 == 0) atomicAdd(&cnt[t], 1.0f);
}

// pre[n,OD] = (agg[n]/max(cnt,1)) @ Wl + xin @ Wr + bias   (K concat, FFMA2)
// Pipelined staging: W via cp.async, A via prefetched float4 LDG (one kt ahead).
// Epilogue: per-column sum/sumsq into bnacc; last block computes scale/shift.
template<int KD, int OD, int BM, int CG>
__global__ void __launch_bounds__(256)
gemm_dual5(const float* __restrict__ agg, const float* __restrict__ cnt,
           const float* __restrict__ xin,
           const float* __restrict__ Wl, const float* __restrict__ Wr,
           const float* __restrict__ bias, float* __restrict__ outp,
           float* __restrict__ bnacc, int* __restrict__ ctr,
           const float* __restrict__ bng, const float* __restrict__ bnb,
           float* __restrict__ scale, float* __restrict__ shift,
           float invn)
{
    const int TN = 8, BK = 32, ASTR = BM + 4;
    const int NTY = 256 / CG;            // = BM/8
    const int NK  = 2 * KD / BK;
    const int ALD = BM * BK / (4 * 256); // float4 A loads per thread per kt
    const int WLD = BK * OD / (4 * 256); // 16B W copies per thread per kt
    extern __shared__ float sh[];
    float* sW = sh;             // BK*OD
    float* sA = sh + BK * OD;   // BK*ASTR

    int tid = threadIdx.x;
    int tx  = tid % CG;
    int ty  = tid / CG;
    int row0 = blockIdx.x * BM;

    unsigned long long acc[4][TN];
#pragma unroll
    for (int r = 0; r < 4; r++)
#pragma unroll
        for (int j = 0; j < TN; j++) acc[r][j] = 0ull;

    float4 areg[ALD];
    float  ainv[ALD];

    // prefetch A tile 0
#pragma unroll
    for (int j = 0; j < ALD; j++) {
        int idx = tid + j * 256;          // over BM*(BK/4)
        int m = idx >> 3, kq = idx & 7;   // BK/4 = 8
        int row = row0 + m;
        int kg = 4 * kq;                  // kt=0
        if (kg < KD) {
            areg[j] = *reinterpret_cast<const float4*>(&agg[(size_t)row * KD + kg]);
            ainv[j] = 1.f / fmaxf(cnt[row], 1.f);
        } else {
            areg[j] = *reinterpret_cast<const float4*>(&xin[(size_t)row * KD + (kg - KD)]);
            ainv[j] = 1.f;
        }
    }

    for (int kti = 0; kti < NK; kti++) {
        int kt = kti * BK;
        __syncthreads();   // previous compute done; smem free

        // W tile via cp.async (row-major pure copy)
#pragma unroll
        for (int j = 0; j < WLD; j++) {
            int idx = tid + j * 256;                 // over BK*(OD/4)
            int k = idx / (OD / 4), cq = idx % (OD / 4);
            int kg = kt + k;
            const float* gsrc = (kg < KD) ? &Wl[(size_t)kg * OD + 4 * cq]
                                          : &Wr[(size_t)(kg - KD) * OD + 4 * cq];
            cp_async16(&sW[k * OD + 4 * cq], gsrc);
        }
        asm volatile("cp.async.commit_group;" ::: "memory");

        // A tile STS (transpose + mean-div) from prefetched regs
#pragma unroll
        for (int j = 0; j < ALD; j++) {
            int idx = tid + j * 256;
            int m = idx >> 3, kq = idx & 7;
            float iv = ainv[j];
            sA[(4*kq+0) * ASTR + m] = areg[j].x * iv;
            sA[(4*kq+1) * ASTR + m] = areg[j].y * iv;
            sA[(4*kq+2) * ASTR + m] = areg[j].z * iv;
            sA[(4*kq+3) * ASTR + m] = areg[j].w * iv;
        }

        // prefetch A tile kt+1 (LDG latency overlaps with compute below)
        if (kti + 1 < NK) {
            int ktn = kt + BK;
#pragma unroll
            for (int j = 0; j < ALD; j++) {
                int idx = tid + j * 256;
                int m = idx >> 3, kq = idx & 7;
                int row = row0 + m;
                int kg = ktn + 4 * kq;
                if (kg < KD) {
                    areg[j] = *reinterpret_cast<const float4*>(&agg[(size_t)row * KD + kg]);
                    ainv[j] = 1.f / fmaxf(cnt[row], 1.f);
                } else {
                    areg[j] = *reinterpret_cast<const float4*>(&xin[(size_t)row * KD + (kg - KD)]);
                    ainv[j] = 1.f;
                }
            }
        }

        asm volatile("cp.async.wait_group 0;" ::: "memory");
        __syncthreads();

#pragma unroll
        for (int k = 0; k < BK; k++) {
            const float4 a0 = *reinterpret_cast<const float4*>(&sA[k * ASTR + ty * 8]);
            const float4 a1 = *reinterpret_cast<const float4*>(&sA[k * ASTR + ty * 8 + 4]);
            unsigned long long ap[4] = { pk2(a0.x, a0.y), pk2(a0.z, a0.w),
                                         pk2(a1.x, a1.y), pk2(a1.z, a1.w) };
#pragma unroll
            for (int jj = 0; jj < TN / 4; jj++) {
                float4 w4 = *reinterpret_cast<const float4*>(&sW[k * OD + tx * TN + jj * 4]);
                unsigned long long w0 = pk2(w4.x, w4.x), w1 = pk2(w4.y, w4.y);
                unsigned long long w2 = pk2(w4.z, w4.z), w3 = pk2(w4.w, w4.w);
#pragma unroll
                for (int r = 0; r < 4; r++) {
                    ffma2(acc[r][jj*4+0], ap[r], w0);
                    ffma2(acc[r][jj*4+1], ap[r], w1);
                    ffma2(acc[r][jj*4+2], ap[r], w2);
                    ffma2(acc[r][jj*4+3], ap[r], w3);
                }
            }
        }
    }

    // epilogue: unpack, add bias, store; accumulate column stats
    float cs[TN], cs2[TN];
#pragma unroll
    for (int j = 0; j < TN; j++) { cs[j] = 0.f; cs2[j] = 0.f; }
    float bb[TN];
#pragma unroll
    for (int jj = 0; jj < TN / 4; jj++) {
        float4 b4 = *reinterpret_cast<const float4*>(&bias[tx * TN + jj * 4]);
        bb[jj*4+0]=b4.x; bb[jj*4+1]=b4.y; bb[jj*4+2]=b4.z; bb[jj*4+3]=b4.w;
    }
#pragma unroll
    for (int r = 0; r < 4; r++) {
        float lo[TN], hi[TN];
#pragma unroll
        for (int j = 0; j < TN; j++) {
            upk2(acc[r][j], lo[j], hi[j]);
            lo[j] += bb[j]; hi[j] += bb[j];
            cs[j]  += lo[j] + hi[j];
            cs2[j] += lo[j]*lo[j] + hi[j]*hi[j];
        }
        int row_lo = row0 + ty * 8 + 2 * r;
#pragma unroll
        for (int jj = 0; jj < TN / 4; jj++) {
            int c = tx * TN + jj * 4;
            *reinterpret_cast<float4*>(&outp[(size_t)row_lo * OD + c]) =
                make_float4(lo[jj*4], lo[jj*4+1], lo[jj*4+2], lo[jj*4+3]);
            *reinterpret_cast<float4*>(&outp[(size_t)(row_lo+1) * OD + c]) =
                make_float4(hi[jj*4], hi[jj*4+1], hi[jj*4+2], hi[jj*4+3]);
        }
    }

    // block-level stats reduce (reuse smem), then one atomic per column
    __syncthreads();
    float* sRed = sh;   // NTY*OD floats
#pragma unroll
    for (int j = 0; j < TN; j++) sRed[ty * OD + tx * TN + j] = cs[j];
    __syncthreads();
    for (int c = tid; c < OD; c += 256) {
        float t = 0.f;
#pragma unroll
        for (int i = 0; i < NTY; i++) t += sRed[i * OD + c];
        atomicAdd(&bnacc[c], t);
    }
    __syncthreads();
#pragma unroll
    for (int j = 0; j < TN; j++) sRed[ty * OD + tx * TN + j] = cs2[j];
    __syncthreads();
    for (int c = tid; c < OD; c += 256) {
        float t = 0.f;
#pragma unroll
        for (int i = 0; i < NTY; i++) t += sRed[i * OD + c];
        atomicAdd(&bnacc[OD + c], t);
    }

    // last block computes BN scale/shift
    __shared__ int sDone;
    __threadfence();
    if (tid == 0) {
        int old = atomicAdd(ctr, 1);
        sDone = (old == (int)gridDim.x - 1);
    }
    __syncthreads();
    if (sDone) {
        if (tid < OD) {
            float s  = __ldcg(&bnacc[tid]);
            float s2 = __ldcg(&bnacc[OD + tid]);
            float m   = s * invn;
            float var = s2 * invn - m * m;
            float sc  = rsqrtf(var + 1e-5f) * bng[tid];
            scale[tid] = sc;
            shift[tid] = bnb[tid] - m * sc;
        }
        if (tid == 0) *ctr = 0;
    }
}

// fused: BN apply (registers only) + ReLU + two score dot products. One warp per row.
template<int D>
__global__ void bnad_kernel(const float* __restrict__ pre, const float* __restrict__ scale,
                            const float* __restrict__ shift,
                            const float* __restrict__ wrel, const float* __restrict__ wroot,
                            float* __restrict__ rrel, float* __restrict__ rroot, int nrows)
{
    int w = (blockIdx.x * blockDim.x + threadIdx.x) >> 5;
    int lane = threadIdx.x & 31;
    if (w >= nrows) return;
    const int V = D / 128;
    float s1 = 0.f, s2 = 0.f;
    const float4* rowp = reinterpret_cast<const float4*>(pre + (size_t)w * D);
#pragma unroll
    for (int q = 0; q < V; q++) {
        int c4 = lane + q * 32;
        float4 v  = rowp[c4];
        float4 sc = reinterpret_cast<const float4*>(scale)[c4];
        float4 sh = reinterpret_cast<const float4*>(shift)[c4];
        v.x = fmaxf(fmaf(v.x, sc.x, sh.x), 0.f);
        v.y = fmaxf(fmaf(v.y, sc.y, sh.y), 0.f);
        v.z = fmaxf(fmaf(v.z, sc.z, sh.z), 0.f);
        v.w = fmaxf(fmaf(v.w, sc.w, sh.w), 0.f);
        float4 wr = reinterpret_cast<const float4*>(wrel)[c4];
        float4 wo = reinterpret_cast<const float4*>(wroot)[c4];
        s1 += v.x*wr.x + v.y*wr.y + v.z*wr.z + v.w*wr.w;
        s2 += v.x*wo.x + v.y*wo.y + v.z*wo.z + v.w*wo.w;
    }
#pragma unroll
    for (int o = 16; o; o >>= 1) {
        s1 += __shfl_down_sync(0xFFFFFFFFu, s1, o);
        s2 += __shfl_down_sync(0xFFFFFFFFu, s2, o);
    }
    if (lane == 0) { rrel[w] = s1; rroot[w] = s2; }
}

// scalar segment-sum of rrel[src] into sseg[tgt]
__global__ void escore_kernel(const int* __restrict__ src, const int* __restrict__ tgt,
                              const float* __restrict__ rrel, float* __restrict__ sseg, int nedges)
{
    int e = blockIdx.x * blockDim.x + threadIdx.x;
    if (e >= nedges) return;
    int s = src[e];
    if (s < 0) return;
    atomicAdd(&sseg[tgt[e]], rrel[s]);
}

// per-graph top-K via bitonic sort of (score,idx) keys; set-invariant ordering
template<int NPGT, int KSEL>
__global__ void topk_kernel(const float* __restrict__ sseg, const float* __restrict__ rroot,
                            const float* __restrict__ brel,
                            int* __restrict__ perm, float* __restrict__ tanhv,
                            int* __restrict__ mapping)
{
    __shared__ unsigned long long keys[NPGT];
    int g = blockIdx.x, tid = threadIdx.x;
    float br = brel[0];
    for (int i = tid; i < NPGT; i += blockDim.x) {
        int node = g * NPGT + i;
        float sc = sseg[node] + br + rroot[node];
        unsigned u = __float_as_uint(sc);
        u = (u & 0x80000000u) ? ~u : (u | 0x80000000u);
        keys[i] = ((unsigned long long)u << 32) | (unsigned)i;
    }
    __syncthreads();
    for (int k = 2; k <= NPGT; k <<= 1) {
        for (int j = k >> 1; j > 0; j >>= 1) {
            for (int t = tid; t < NPGT; t += blockDim.x) {
                int ixj = t ^ j;
                if (ixj > t) {
                    unsigned long long a = keys[t], c = keys[ixj];
                    bool desc = ((t & k) == 0);
                    if ((a < c) == desc) { keys[t] = c; keys[ixj] = a; }
                }
            }
            __syncthreads();
        }
    }
    for (int t = tid; t < KSEL; t += blockDim.x) {
        int li = (int)(keys[t] & 0xFFFFFFFFull);
        int node = g * NPGT + li;
        float sc = sseg[node] + br + rroot[node];
        int ni = g * KSEL + t;
        perm[ni]  = node;
        tanhv[ni] = tanhf(sc);
        if (mapping) mapping[node] = ni;
    }
}

// gather + BN/ReLU + tanh-scale (float4)
__global__ void gather_kernel(const float* __restrict__ pre, const int* __restrict__ perm,
                              const float* __restrict__ scale, const float* __restrict__ shift,
                              const float* __restrict__ tv, float* __restrict__ o, int n)
{
    const int V = H1 / 4;  // 32
    int i = blockIdx.x * blockDim.x + threadIdx.x;
    if (i >= n * V) return;
    int node = i / V, off = i - node * V;
    float4 v  = reinterpret_cast<const float4*>(pre)[(size_t)perm[node] * V + off];
    float4 sc = reinterpret_cast<const float4*>(scale)[off];
    float4 sh = reinterpret_cast<const float4*>(shift)[off];
    float t = tv[node];
    v.x = fmaxf(fmaf(v.x, sc.x, sh.x), 0.f) * t;
    v.y = fmaxf(fmaf(v.y, sc.y, sh.y), 0.f) * t;
    v.z = fmaxf(fmaf(v.z, sc.z, sh.z), 0.f) * t;
    v.w = fmaxf(fmaf(v.w, sc.w, sh.w), 0.f) * t;
    reinterpret_cast<float4*>(o)[i] = v;
}

__global__ void remap_kernel(const int* __restrict__ src, const int* __restrict__ tgt,
                             const int* __restrict__ mapping,
                             int* __restrict__ src2, int* __restrict__ tgt2)
{
    int e = blockIdx.x * blockDim.x + threadIdx.x;
    if (e >= Ee) return;
    int s = mapping[src[e]];
    int t = mapping[tgt[e]];
    if (s < 0 || t < 0) { s = -1; t = -1; }
    src2[e] = s; tgt2[e] = t;
}

// per-graph: BN/ReLU on the fly -> pooled mean -> relu -> 256x2 linear -> softmax
__global__ void final_kernel(const float* __restrict__ pre2, const int* __restrict__ perm2,
                             const float* __restrict__ scale, const float* __restrict__ shift,
                             const float* __restrict__ tanhv2, const float* __restrict__ Wlin,
                             const float* __restrict__ blin, float* __restrict__ outp)
{
    int g = blockIdx.x, c = threadIdx.x;   // 256 threads
    __shared__ int   sp[K2];
    __shared__ float st[K2];
    for (int i = c; i < K2; i += 256) { sp[i] = perm2[g * K2 + i]; st[i] = tanhv2[g * K2 + i]; }
    __syncthreads();
    float sc = scale[c], sh = shift[c];
    float acc = 0.f;
#pragma unroll 4
    for (int r = 0; r < K2; r++)
        acc += fmaxf(fmaf(pre2[(size_t)sp[r] * H2 + c], sc, sh), 0.f) * st[r];
    float p = fmaxf(acc * (1.0f / (float)K2), 0.f);
    __shared__ float red0[256], red1[256];
    red0[c] = p * Wlin[c * 2 + 0];
    red1[c] = p * Wlin[c * 2 + 1];
    __syncthreads();
    for (int s = 128; s; s >>= 1) {
        if (c < s) { red0[c] += red0[c + s]; red1[c] += red1[c + s]; }
        __syncthreads();
    }
    if (c == 0) {
        float a = red0[0] + blin[0];
        float b = red1[0] + blin[1];
        float m = fmaxf(a, b);
        float ea = expf(a - m), eb = expf(b - m);
        float inv = 1.f / (ea + eb);
        outp[g * 2 + 0] = ea * inv;
        outp[g * 2 + 1] = eb * inv;
    }
}

// ---------------- host launch ----------------
template <typename T>
static void* symaddr(const T& s) { void* p = nullptr; cudaGetSymbolAddress(&p, s); return p; }

extern "C" void kernel_launch(void* const* d_in, const int* in_sizes, int n_in,
                              void* d_out, int out_size)
{
    const float* x     = (const float*)d_in[0];
    const int*   ei    = (const int*)  d_in[1];
    const int*   src   = ei;
    const int*   tgt   = ei + Ee;
    const float* W1l   = (const float*)d_in[3];
    const float* b1l   = (const float*)d_in[4];
    const float* W1r   = (const float*)d_in[5];
    const float* bn1g  = (const float*)d_in[6];
    const float* bn1b  = (const float*)d_in[7];
    const float* p1Wrel  = (const float*)d_in[8];
    const float* p1brel  = (const float*)d_in[9];
    const float* p1Wroot = (const float*)d_in[10];
    const float* W2l   = (const float*)d_in[11];
    const float* b2l   = (const float*)d_in[12];
    const float* W2r   = (const float*)d_in[13];
    const float* bn2g  = (const float*)d_in[14];
    const float* bn2b  = (const float*)d_in[15];
    const float* p2Wrel  = (const float*)d_in[16];
    const float* p2brel  = (const float*)d_in[17];
    const float* p2Wroot = (const float*)d_in[18];
    const float* Wlin  = (const float*)d_in[19];
    const float* blin  = (const float*)d_in[20];
    float* out = (float*)d_out;

    float* z1    = (float*)symaddr(g_z1);
    float* agg1  = z1;
    float* cnt1  = z1 + Nn*IND;
    float* sseg1 = cnt1 + Nn;
    float* bnacc1= sseg1 + Nn;
    float* z2    = (float*)symaddr(g_z2);
    float* agg2  = z2;
    float* cnt2  = z2 + N1*H1;
    float* sseg2 = cnt2 + N1;
    float* bnacc2= sseg2 + N1;

    float* rrel1 = (float*)symaddr(g_rrel1);
    float* rroot1= (float*)symaddr(g_rroot1);
    float* pre1  = (float*)symaddr(g_pre1);
    int*   map1  = (int*)  symaddr(g_map1);
    int*   perm1 = (int*)  symaddr(g_perm1);
    float* tanh1 = (float*)symaddr(g_tanh1);
    int*   src2  = (int*)  symaddr(g_src2);
    int*   tgt2  = (int*)  symaddr(g_tgt2);
    float* h1new = (float*)symaddr(g_h1new);
    float* rrel2 = (float*)symaddr(g_rrel2);
    float* rroot2= (float*)symaddr(g_rroot2);
    float* pre2  = (float*)symaddr(g_pre2);
    int*   perm2 = (int*)  symaddr(g_perm2);
    float* tanh2 = (float*)symaddr(g_tanh2);
    float* scale = (float*)symaddr(g_scale);
    float* shift = (float*)symaddr(g_shift);
    int*   ctr1  = (int*)  symaddr(g_ctr1);
    int*   ctr2  = (int*)  symaddr(g_ctr2);

    // smem: stage1 (32*128 + 32*132)*4 = 33280 ; stage2 (32*256 + 32*68)*4 = 41472
    cudaFuncSetAttribute((const void*)gemm_dual5<IND, H1, 128, 16>,
                         cudaFuncAttributeMaxDynamicSharedMemorySize, 33280);
    cudaFuncSetAttribute((const void*)gemm_dual5<H1, H2, 64, 32>,
                         cudaFuncAttributeMaxDynamicSharedMemorySize, 41472);

    // ---- zero-fill (all up front) ----
    cudaMemsetAsync(z1, 0, sizeof(float)*Z1_FLOATS);
    cudaMemsetAsync(z2, 0, sizeof(float)*Z2_FLOATS);
    cudaMemsetAsync(map1, 0xFF, sizeof(int)*Nn);   // -1

    // ---- stage 1 ----
    agg_kernel<IND><<<(Ee*(IND/4))/256, 256>>>(src, tgt, x, agg1, cnt1, Ee);
    gemm_dual5<IND, H1, 128, 16><<<Nn/128, 256, 33280>>>(
        agg1, cnt1, x, W1l, W1r, b1l, pre1,
        bnacc1, ctr1, bn1g, bn1b, scale, shift, 1.f/(float)Nn);
    bnad_kernel<H1><<<Nn/8, 256>>>(pre1, scale, shift, p1Wrel, p1Wroot, rrel1, rroot1, Nn);
    escore_kernel<<<Ee/256, 256>>>(src, tgt, rrel1, sseg1, Ee);
    topk_kernel<NPG, K1><<<Bg, 1024>>>(sseg1, rroot1, p1brel, perm1, tanh1, map1);
    gather_kernel<<<(N1*(H1/4))/256, 256>>>(pre1, perm1, scale, shift, tanh1, h1new, N1);
    remap_kernel<<<Ee/256, 256>>>(src, tgt, map1, src2, tgt2);

    // ---- stage 2 ----
    agg_kernel<H1><<<(Ee*(H1/4))/256, 256>>>(src2, tgt2, h1new, agg2, cnt2, Ee);
    gemm_dual5<H1, H2, 64, 32><<<N1/64, 256, 41472>>>(
        agg2, cnt2, h1new, W2l, W2r, b2l, pre2,
        bnacc2, ctr2, bn2g, bn2b, scale, shift, 1.f/(float)N1);
    bnad_kernel<H2><<<N1/8, 256>>>(pre2, scale, shift, p2Wrel, p2Wroot, rrel2, rroot2, N1);
    escore_kernel<<<Ee/256, 256>>>(src2, tgt2, rrel2, sseg2, Ee);
    topk_kernel<K1, K2><<<Bg, 1024>>>(sseg2, rroot2, p2brel, perm2, tanh2, nullptr);

    // ---- readout ----
    final_kernel<<<Bg, 256>>>(pre2, perm2, scale, shift, tanh2, Wlin, blin, out);

    (void)in_sizes; (void)n_in; (void)out_size;
}